// round 13
// baseline (speedup 1.0000x reference)
#include <cuda_runtime.h>
#include <math.h>

// RMSD (Kabsch-aligned MSE). Per-WARP independent TMA pipelines (DEPTH=2),
// 9 warps/CTA, early refill, L2 evict_first streaming hint.
// 148 persistent CTAs x 288 threads.

constexpr int NB   = 8192;
constexpr int GRID = 148;
constexpr int WPB  = 9;                    // warps per CTA
constexpr int NW   = GRID * WPB;           // 1332 warp pipelines
constexpr int DEPTH = 2;                   // slots per warp
constexpr int TBYTES = 512 * 3 * 4;        // 6144 per tensor per batch
constexpr int SLOT_BYTES = 2 * TBYTES;     // 12288 (x | y)
constexpr int SMEM_BYTES = WPB * DEPTH * SLOT_BYTES;  // 221184 (216KB)

__device__ double       g_partial[GRID];
__device__ unsigned int g_count = 0;

__device__ __forceinline__ unsigned smem_u32(const void* p) {
    return (unsigned)__cvta_generic_to_shared(p);
}
__device__ __forceinline__ unsigned long long mk_policy() {
    unsigned long long pol;
    asm("createpolicy.fractional.L2::evict_first.b64 %0, 1.0;" : "=l"(pol));
    return pol;
}
__device__ __forceinline__ void bulk_cp(unsigned dst, const void* src, unsigned bytes,
                                        unsigned mbar, unsigned long long pol) {
    asm volatile(
        "cp.async.bulk.shared::cluster.global.mbarrier::complete_tx::bytes.L2::cache_hint "
        "[%0], [%1], %2, [%3], %4;"
        :: "r"(dst), "l"(src), "r"(bytes), "r"(mbar), "l"(pol) : "memory");
}
__device__ __forceinline__ void mbar_init(unsigned mbar, unsigned count) {
    asm volatile("mbarrier.init.shared.b64 [%0], %1;" :: "r"(mbar), "r"(count) : "memory");
}
__device__ __forceinline__ void mbar_expect_tx(unsigned mbar, unsigned tx) {
    asm volatile("mbarrier.arrive.expect_tx.shared.b64 _, [%0], %1;"
                 :: "r"(mbar), "r"(tx) : "memory");
}
__device__ __forceinline__ void mbar_wait(unsigned mbar, unsigned parity) {
    asm volatile(
        "{\n\t"
        ".reg .pred P;\n\t"
        "WAIT_%=:\n\t"
        "mbarrier.try_wait.parity.acquire.cta.shared::cta.b64 P, [%0], %1, 0x989680;\n\t"
        "@P bra.uni DONE_%=;\n\t"
        "bra.uni WAIT_%=;\n\t"
        "DONE_%=:\n\t"
        "}"
        :: "r"(mbar), "r"(parity) : "memory");
}

// fin[16]: 0-2 Sx, 3-5 Sy, 6 S|x|^2+S|y|^2, 7..15 raw C row-major
__device__ __forceinline__ float kabsch_loss(const float* fin)
{
    const float n = 512.f;
    const float invn = 1.f / n;
    float mx[3], my[3];
#pragma unroll
    for (int d = 0; d < 3; d++) { mx[d] = fin[d] * invn; my[d] = fin[3 + d] * invn; }

    float C[3][3];
#pragma unroll
    for (int d = 0; d < 3; d++)
#pragma unroll
        for (int e = 0; e < 3; e++)
            C[d][e] = fin[7 + 3*d + e] - n * mx[d] * my[e];

    float sxy = fin[6] - n * (mx[0]*mx[0] + mx[1]*mx[1] + mx[2]*mx[2]
                            + my[0]*my[0] + my[1]*my[1] + my[2]*my[2]);

    float a00 = C[0][0]*C[0][0] + C[1][0]*C[1][0] + C[2][0]*C[2][0];
    float a11 = C[0][1]*C[0][1] + C[1][1]*C[1][1] + C[2][1]*C[2][1];
    float a22 = C[0][2]*C[0][2] + C[1][2]*C[1][2] + C[2][2]*C[2][2];
    float a01 = C[0][0]*C[0][1] + C[1][0]*C[1][1] + C[2][0]*C[2][1];
    float a02 = C[0][0]*C[0][2] + C[1][0]*C[1][2] + C[2][0]*C[2][2];
    float a12 = C[0][1]*C[0][2] + C[1][1]*C[1][2] + C[2][1]*C[2][2];

    float q  = (a00 + a11 + a22) * (1.f / 3.f);
    float p1 = a01*a01 + a02*a02 + a12*a12;
    float b00 = a00 - q, b11 = a11 - q, b22 = a22 - q;
    float p2 = b00*b00 + b11*b11 + b22*b22 + 2.f * p1;
    float p  = sqrtf(fmaxf(p2, 1e-30f) * (1.f / 6.f));
    float ip = 1.f / p;
    float detB = ( b00 * (b11*b22 - a12*a12)
                 - a01 * (a01*b22 - a12*a02)
                 + a02 * (a01*a12 - b11*a02) ) * (ip * ip * ip);
    float r = fminf(fmaxf(0.5f * detB, -1.f), 1.f);
    float phi = acosf(r) * (1.f / 3.f);
    float e0 = q + 2.f * p * cosf(phi);
    float e2 = q + 2.f * p * cosf(phi + 2.0943951023931953f);
    float e1 = 3.f * q - e0 - e2;

    float s0 = sqrtf(fmaxf(e0, 0.f));
    float s1 = sqrtf(fmaxf(e1, 0.f));
    float s2 = sqrtf(fmaxf(e2, 0.f));

    float detC = C[0][0]*(C[1][1]*C[2][2] - C[1][2]*C[2][1])
               - C[0][1]*(C[1][0]*C[2][2] - C[1][2]*C[2][0])
               + C[0][2]*(C[1][0]*C[2][1] - C[1][1]*C[2][0]);
    float sgn = (detC < 0.f) ? -1.f : 1.f;

    return sxy - 2.f * (s0 + s1 + sgn * s2);
}

__global__ __launch_bounds__(288)
void rmsd_fused_kernel(const char* __restrict__ xg, const char* __restrict__ yg,
                       float* __restrict__ out)
{
    extern __shared__ char smem[];                   // [WPB][DEPTH][x 6144 | y 6144]
    __shared__ unsigned long long mbar_store[WPB][DEPTH];
    __shared__ double wl[WPB];
    __shared__ int    is_last;

    const int tid  = threadIdx.x;
    const int w    = tid >> 5;
    const int lane = tid & 31;
    const int gw   = blockIdx.x * WPB + w;            // global warp pipeline id

    const unsigned smem_base = smem_u32(smem);
    const unsigned warp_smem = smem_base + w * DEPTH * SLOT_BYTES;
    const unsigned mb[2] = { smem_u32(&mbar_store[w][0]), smem_u32(&mbar_store[w][1]) };
    const unsigned long long pol = mk_policy();

    if (lane == 0) { mbar_init(mb[0], 1); mbar_init(mb[1], 1); }
    __syncthreads();   // all mbarriers initialized before any TMA

    const int total = (NB - gw + NW - 1) / NW;        // 6 or 7 batches

    auto issue = [&](int j) {                          // lane 0 only
        const int gb = gw + j * NW;
        const int slot = j & 1;
        const size_t goff = (size_t)gb * TBYTES;
        const unsigned dst = warp_smem + slot * SLOT_BYTES;
        mbar_expect_tx(mb[slot], SLOT_BYTES);
        bulk_cp(dst,          xg + goff, TBYTES, mb[slot], pol);
        bulk_cp(dst + TBYTES, yg + goff, TBYTES, mb[slot], pol);
    };

    if (lane == 0) {
        if (total > 0) issue(0);
        if (total > 1) issue(1);
    }
    __syncwarp();

    double local_loss = 0.0;

    for (int j = 0; j < total; j++) {
        const int slot = j & 1;
        mbar_wait(mb[slot], (j >> 1) & 1);            // all lanes acquire

        const float4* sx = reinterpret_cast<const float4*>(
            smem + (size_t)w * DEPTH * SLOT_BYTES + (size_t)slot * SLOT_BYTES);
        const float4* sy = sx + TBYTES / 16;

        float v[16];
#pragma unroll
        for (int i = 0; i < 16; i++) v[i] = 0.f;

#pragma unroll
        for (int c = 0; c < 4; c++) {
            const int g = c * 32 + lane;              // 4-point group
            float4 xa = sx[3*g], xb = sx[3*g + 1], xc = sx[3*g + 2];
            float4 ya = sy[3*g], yb = sy[3*g + 1], yc = sy[3*g + 2];

            float X[4][3] = {{xa.x, xa.y, xa.z}, {xa.w, xb.x, xb.y},
                             {xb.z, xb.w, xc.x}, {xc.y, xc.z, xc.w}};
            float Y[4][3] = {{ya.x, ya.y, ya.z}, {ya.w, yb.x, yb.y},
                             {yb.z, yb.w, yc.x}, {yc.y, yc.z, yc.w}};
#pragma unroll
            for (int pnt = 0; pnt < 4; pnt++) {
#pragma unroll
                for (int d = 0; d < 3; d++) {
                    v[d]     += X[pnt][d];
                    v[3 + d] += Y[pnt][d];
                    v[6]     += X[pnt][d] * X[pnt][d];
                    v[6]     += Y[pnt][d] * Y[pnt][d];
#pragma unroll
                    for (int e = 0; e < 3; e++)
                        v[7 + 3*d + e] += X[pnt][d] * Y[pnt][e];
                }
            }
        }

        // Slot fully read into registers -> refill NOW, before the reduction,
        // so the next copy overlaps the SHFL tree + kabsch tail.
        __syncwarp();
        if (lane == 0 && j + DEPTH < total) issue(j + DEPTH);

        // Paired-value warp reduction: 8 pairs, 6 SHFL each + 1 gather.
        float fin[16];
#pragma unroll
        for (int i = 0; i < 8; i++) {
            float a = v[2*i]     + __shfl_xor_sync(0xffffffffu, v[2*i],     16);
            float b = v[2*i + 1] + __shfl_xor_sync(0xffffffffu, v[2*i + 1], 16);
            float c = (lane < 16) ? a : b;
#pragma unroll
            for (int o = 8; o > 0; o >>= 1)
                c += __shfl_xor_sync(0xffffffffu, c, o);
            float odd = __shfl_sync(0xffffffffu, c, 16);
            fin[2*i]     = c;      // valid on lane 0
            fin[2*i + 1] = odd;
        }

        if (lane == 0) local_loss += (double)kabsch_loss(fin);
    }

    if (lane == 0) wl[w] = local_loss;
    __syncthreads();

    if (tid == 0) {
        double s = 0.0;
#pragma unroll
        for (int i = 0; i < WPB; i++) s += wl[i];
        g_partial[blockIdx.x] = s;
        __threadfence();
        unsigned done = atomicAdd(&g_count, 1u);
        is_last = (done == GRID - 1) ? 1 : 0;
    }
    __syncthreads();

    if (is_last) {
        __threadfence();
        volatile double* gp = g_partial;
        double s = (tid < GRID) ? gp[tid] : 0.0;

#pragma unroll
        for (int o = 16; o > 0; o >>= 1)
            s += __shfl_down_sync(0xffffffffu, s, o);

        __shared__ double sm[WPB];
        if (lane == 0) sm[w] = s;
        __syncthreads();
        if (tid == 0) {
            double tot = 0.0;
#pragma unroll
            for (int i = 0; i < WPB; i++) tot += sm[i];
            out[0] = (float)(tot / ((double)NB * 512.0 * 3.0));
            g_count = 0;   // reset for graph replay
        }
    }
}

extern "C" void kernel_launch(void* const* d_in, const int* in_sizes, int n_in,
                              void* d_out, int out_size)
{
    const char* inp = (const char*)d_in[0];
    const char* tgt = (const char*)d_in[1];
    float* out = (float*)d_out;

    static int configured = 0;
    if (!configured) {
        cudaFuncSetAttribute(rmsd_fused_kernel,
                             cudaFuncAttributeMaxDynamicSharedMemorySize, SMEM_BYTES);
        configured = 1;
    }
    rmsd_fused_kernel<<<GRID, 288, SMEM_BYTES>>>(inp, tgt, out);
}

// round 14
// speedup vs baseline: 1.1048x; 1.1048x over previous
#include <cuda_runtime.h>
#include <math.h>

// RMSD (Kabsch-aligned MSE). Per-WARP independent TMA pipelines (DEPTH=2),
// 8 warps/CTA, 148 persistent CTAs x 256 threads. Identical to the 18.9us
// best except: slot refill is issued immediately after the accumulate loop
// (before the SHFL reduction tree), shortening the copy-issue latency path.

constexpr int NB   = 8192;
constexpr int GRID = 148;
constexpr int WPB  = 8;                    // warps per CTA
constexpr int NW   = GRID * WPB;           // 1184 warp pipelines
constexpr int DEPTH = 2;                   // slots per warp
constexpr int TBYTES = 512 * 3 * 4;        // 6144 per tensor per batch
constexpr int SLOT_BYTES = 2 * TBYTES;     // 12288 (x | y)
constexpr int SMEM_BYTES = WPB * DEPTH * SLOT_BYTES;  // 196608

__device__ double       g_partial[GRID];
__device__ unsigned int g_count = 0;

__device__ __forceinline__ unsigned smem_u32(const void* p) {
    return (unsigned)__cvta_generic_to_shared(p);
}
__device__ __forceinline__ void bulk_cp(unsigned dst, const void* src, unsigned bytes,
                                        unsigned mbar) {
    asm volatile(
        "cp.async.bulk.shared::cluster.global.mbarrier::complete_tx::bytes "
        "[%0], [%1], %2, [%3];"
        :: "r"(dst), "l"(src), "r"(bytes), "r"(mbar) : "memory");
}
__device__ __forceinline__ void mbar_init(unsigned mbar, unsigned count) {
    asm volatile("mbarrier.init.shared.b64 [%0], %1;" :: "r"(mbar), "r"(count) : "memory");
}
__device__ __forceinline__ void mbar_expect_tx(unsigned mbar, unsigned tx) {
    asm volatile("mbarrier.arrive.expect_tx.shared.b64 _, [%0], %1;"
                 :: "r"(mbar), "r"(tx) : "memory");
}
__device__ __forceinline__ void mbar_wait(unsigned mbar, unsigned parity) {
    asm volatile(
        "{\n\t"
        ".reg .pred P;\n\t"
        "WAIT_%=:\n\t"
        "mbarrier.try_wait.parity.acquire.cta.shared::cta.b64 P, [%0], %1, 0x989680;\n\t"
        "@P bra.uni DONE_%=;\n\t"
        "bra.uni WAIT_%=;\n\t"
        "DONE_%=:\n\t"
        "}"
        :: "r"(mbar), "r"(parity) : "memory");
}

// fin[16]: 0-2 Sx, 3-5 Sy, 6 S|x|^2+S|y|^2, 7..15 raw C row-major
__device__ __forceinline__ float kabsch_loss(const float* fin)
{
    const float n = 512.f;
    const float invn = 1.f / n;
    float mx[3], my[3];
#pragma unroll
    for (int d = 0; d < 3; d++) { mx[d] = fin[d] * invn; my[d] = fin[3 + d] * invn; }

    float C[3][3];
#pragma unroll
    for (int d = 0; d < 3; d++)
#pragma unroll
        for (int e = 0; e < 3; e++)
            C[d][e] = fin[7 + 3*d + e] - n * mx[d] * my[e];

    float sxy = fin[6] - n * (mx[0]*mx[0] + mx[1]*mx[1] + mx[2]*mx[2]
                            + my[0]*my[0] + my[1]*my[1] + my[2]*my[2]);

    float a00 = C[0][0]*C[0][0] + C[1][0]*C[1][0] + C[2][0]*C[2][0];
    float a11 = C[0][1]*C[0][1] + C[1][1]*C[1][1] + C[2][1]*C[2][1];
    float a22 = C[0][2]*C[0][2] + C[1][2]*C[1][2] + C[2][2]*C[2][2];
    float a01 = C[0][0]*C[0][1] + C[1][0]*C[1][1] + C[2][0]*C[2][1];
    float a02 = C[0][0]*C[0][2] + C[1][0]*C[1][2] + C[2][0]*C[2][2];
    float a12 = C[0][1]*C[0][2] + C[1][1]*C[1][2] + C[2][1]*C[2][2];

    float q  = (a00 + a11 + a22) * (1.f / 3.f);
    float p1 = a01*a01 + a02*a02 + a12*a12;
    float b00 = a00 - q, b11 = a11 - q, b22 = a22 - q;
    float p2 = b00*b00 + b11*b11 + b22*b22 + 2.f * p1;
    float p  = sqrtf(fmaxf(p2, 1e-30f) * (1.f / 6.f));
    float ip = 1.f / p;
    float detB = ( b00 * (b11*b22 - a12*a12)
                 - a01 * (a01*b22 - a12*a02)
                 + a02 * (a01*a12 - b11*a02) ) * (ip * ip * ip);
    float r = fminf(fmaxf(0.5f * detB, -1.f), 1.f);
    float phi = acosf(r) * (1.f / 3.f);
    float e0 = q + 2.f * p * cosf(phi);
    float e2 = q + 2.f * p * cosf(phi + 2.0943951023931953f);
    float e1 = 3.f * q - e0 - e2;

    float s0 = sqrtf(fmaxf(e0, 0.f));
    float s1 = sqrtf(fmaxf(e1, 0.f));
    float s2 = sqrtf(fmaxf(e2, 0.f));

    float detC = C[0][0]*(C[1][1]*C[2][2] - C[1][2]*C[2][1])
               - C[0][1]*(C[1][0]*C[2][2] - C[1][2]*C[2][0])
               + C[0][2]*(C[1][0]*C[2][1] - C[1][1]*C[2][0]);
    float sgn = (detC < 0.f) ? -1.f : 1.f;

    return sxy - 2.f * (s0 + s1 + sgn * s2);
}

__global__ __launch_bounds__(256)
void rmsd_fused_kernel(const char* __restrict__ xg, const char* __restrict__ yg,
                       float* __restrict__ out)
{
    extern __shared__ char smem[];                   // [WPB][DEPTH][x 6144 | y 6144]
    __shared__ unsigned long long mbar_store[WPB][DEPTH];
    __shared__ double wl[WPB];
    __shared__ int    is_last;

    const int tid  = threadIdx.x;
    const int w    = tid >> 5;
    const int lane = tid & 31;
    const int gw   = blockIdx.x * WPB + w;            // global warp pipeline id

    const unsigned smem_base = smem_u32(smem);
    const unsigned warp_smem = smem_base + w * DEPTH * SLOT_BYTES;
    const unsigned mb[2] = { smem_u32(&mbar_store[w][0]), smem_u32(&mbar_store[w][1]) };

    if (lane == 0) { mbar_init(mb[0], 1); mbar_init(mb[1], 1); }
    __syncthreads();   // all mbarriers initialized before any TMA

    const int total = (NB - gw + NW - 1) / NW;        // batches for this warp (6 or 7)

    auto issue = [&](int j) {                          // lane 0 only
        const int gb = gw + j * NW;
        const int slot = j & 1;
        const size_t goff = (size_t)gb * TBYTES;
        const unsigned dst = warp_smem + slot * SLOT_BYTES;
        mbar_expect_tx(mb[slot], SLOT_BYTES);
        bulk_cp(dst,          xg + goff, TBYTES, mb[slot]);
        bulk_cp(dst + TBYTES, yg + goff, TBYTES, mb[slot]);
    };

    if (lane == 0) {
        if (total > 0) issue(0);
        if (total > 1) issue(1);
    }
    __syncwarp();

    double local_loss = 0.0;

    for (int j = 0; j < total; j++) {
        const int slot = j & 1;
        mbar_wait(mb[slot], (j >> 1) & 1);            // all lanes acquire

        const float4* sx = reinterpret_cast<const float4*>(
            smem + (size_t)w * DEPTH * SLOT_BYTES + (size_t)slot * SLOT_BYTES);
        const float4* sy = sx + TBYTES / 16;

        float v[16];
#pragma unroll
        for (int i = 0; i < 16; i++) v[i] = 0.f;

#pragma unroll
        for (int c = 0; c < 4; c++) {
            const int g = c * 32 + lane;              // 4-point group
            float4 xa = sx[3*g], xb = sx[3*g + 1], xc = sx[3*g + 2];
            float4 ya = sy[3*g], yb = sy[3*g + 1], yc = sy[3*g + 2];

            float X[4][3] = {{xa.x, xa.y, xa.z}, {xa.w, xb.x, xb.y},
                             {xb.z, xb.w, xc.x}, {xc.y, xc.z, xc.w}};
            float Y[4][3] = {{ya.x, ya.y, ya.z}, {ya.w, yb.x, yb.y},
                             {yb.z, yb.w, yc.x}, {yc.y, yc.z, yc.w}};
#pragma unroll
            for (int pnt = 0; pnt < 4; pnt++) {
#pragma unroll
                for (int d = 0; d < 3; d++) {
                    v[d]     += X[pnt][d];
                    v[3 + d] += Y[pnt][d];
                    v[6]     += X[pnt][d] * X[pnt][d];
                    v[6]     += Y[pnt][d] * Y[pnt][d];
#pragma unroll
                    for (int e = 0; e < 3; e++)
                        v[7 + 3*d + e] += X[pnt][d] * Y[pnt][e];
                }
            }
        }

        // Slot contents fully in registers -> refill NOW, ahead of the
        // SHFL reduction tree, so the copy overlaps reduce + kabsch.
        __syncwarp();
        if (lane == 0 && j + DEPTH < total) issue(j + DEPTH);

        // Paired-value warp reduction: 8 pairs, 6 SHFL each + 1 gather.
        float fin[16];
#pragma unroll
        for (int i = 0; i < 8; i++) {
            float a = v[2*i]     + __shfl_xor_sync(0xffffffffu, v[2*i],     16);
            float b = v[2*i + 1] + __shfl_xor_sync(0xffffffffu, v[2*i + 1], 16);
            float c = (lane < 16) ? a : b;
#pragma unroll
            for (int o = 8; o > 0; o >>= 1)
                c += __shfl_xor_sync(0xffffffffu, c, o);
            float odd = __shfl_sync(0xffffffffu, c, 16);
            fin[2*i]     = c;      // valid on lane 0
            fin[2*i + 1] = odd;
        }

        if (lane == 0) local_loss += (double)kabsch_loss(fin);
    }

    if (lane == 0) wl[w] = local_loss;
    __syncthreads();

    if (tid == 0) {
        double s = 0.0;
#pragma unroll
        for (int i = 0; i < WPB; i++) s += wl[i];
        g_partial[blockIdx.x] = s;
        __threadfence();
        unsigned done = atomicAdd(&g_count, 1u);
        is_last = (done == GRID - 1) ? 1 : 0;
    }
    __syncthreads();

    if (is_last) {
        __threadfence();
        volatile double* gp = g_partial;
        double s = (tid < GRID) ? gp[tid] : 0.0;

#pragma unroll
        for (int o = 16; o > 0; o >>= 1)
            s += __shfl_down_sync(0xffffffffu, s, o);

        __shared__ double sm[8];
        if (lane == 0) sm[w] = s;
        __syncthreads();
        if (tid == 0) {
            double tot = 0.0;
#pragma unroll
            for (int i = 0; i < 8; i++) tot += sm[i];
            out[0] = (float)(tot / ((double)NB * 512.0 * 3.0));
            g_count = 0;   // reset for graph replay
        }
    }
}

extern "C" void kernel_launch(void* const* d_in, const int* in_sizes, int n_in,
                              void* d_out, int out_size)
{
    const char* inp = (const char*)d_in[0];
    const char* tgt = (const char*)d_in[1];
    float* out = (float*)d_out;

    static int configured = 0;
    if (!configured) {
        cudaFuncSetAttribute(rmsd_fused_kernel,
                             cudaFuncAttributeMaxDynamicSharedMemorySize, SMEM_BYTES);
        configured = 1;
    }
    rmsd_fused_kernel<<<GRID, 256, SMEM_BYTES>>>(inp, tgt, out);
}

// round 15
// speedup vs baseline: 1.1067x; 1.0017x over previous
#include <cuda_runtime.h>
#include <math.h>

// RMSD (Kabsch-aligned MSE). Per-WARP independent TMA pipelines (DEPTH=2),
// 8 warps/CTA, 148 persistent CTAs x 256 threads. Identical to the 18.9us
// best except: slot refill is issued immediately after the accumulate loop
// (before the SHFL reduction tree), shortening the copy-issue latency path.

constexpr int NB   = 8192;
constexpr int GRID = 148;
constexpr int WPB  = 8;                    // warps per CTA
constexpr int NW   = GRID * WPB;           // 1184 warp pipelines
constexpr int DEPTH = 2;                   // slots per warp
constexpr int TBYTES = 512 * 3 * 4;        // 6144 per tensor per batch
constexpr int SLOT_BYTES = 2 * TBYTES;     // 12288 (x | y)
constexpr int SMEM_BYTES = WPB * DEPTH * SLOT_BYTES;  // 196608

__device__ double       g_partial[GRID];
__device__ unsigned int g_count = 0;

__device__ __forceinline__ unsigned smem_u32(const void* p) {
    return (unsigned)__cvta_generic_to_shared(p);
}
__device__ __forceinline__ void bulk_cp(unsigned dst, const void* src, unsigned bytes,
                                        unsigned mbar) {
    asm volatile(
        "cp.async.bulk.shared::cluster.global.mbarrier::complete_tx::bytes "
        "[%0], [%1], %2, [%3];"
        :: "r"(dst), "l"(src), "r"(bytes), "r"(mbar) : "memory");
}
__device__ __forceinline__ void mbar_init(unsigned mbar, unsigned count) {
    asm volatile("mbarrier.init.shared.b64 [%0], %1;" :: "r"(mbar), "r"(count) : "memory");
}
__device__ __forceinline__ void mbar_expect_tx(unsigned mbar, unsigned tx) {
    asm volatile("mbarrier.arrive.expect_tx.shared.b64 _, [%0], %1;"
                 :: "r"(mbar), "r"(tx) : "memory");
}
__device__ __forceinline__ void mbar_wait(unsigned mbar, unsigned parity) {
    asm volatile(
        "{\n\t"
        ".reg .pred P;\n\t"
        "WAIT_%=:\n\t"
        "mbarrier.try_wait.parity.acquire.cta.shared::cta.b64 P, [%0], %1, 0x989680;\n\t"
        "@P bra.uni DONE_%=;\n\t"
        "bra.uni WAIT_%=;\n\t"
        "DONE_%=:\n\t"
        "}"
        :: "r"(mbar), "r"(parity) : "memory");
}

// fin[16]: 0-2 Sx, 3-5 Sy, 6 S|x|^2+S|y|^2, 7..15 raw C row-major
__device__ __forceinline__ float kabsch_loss(const float* fin)
{
    const float n = 512.f;
    const float invn = 1.f / n;
    float mx[3], my[3];
#pragma unroll
    for (int d = 0; d < 3; d++) { mx[d] = fin[d] * invn; my[d] = fin[3 + d] * invn; }

    float C[3][3];
#pragma unroll
    for (int d = 0; d < 3; d++)
#pragma unroll
        for (int e = 0; e < 3; e++)
            C[d][e] = fin[7 + 3*d + e] - n * mx[d] * my[e];

    float sxy = fin[6] - n * (mx[0]*mx[0] + mx[1]*mx[1] + mx[2]*mx[2]
                            + my[0]*my[0] + my[1]*my[1] + my[2]*my[2]);

    float a00 = C[0][0]*C[0][0] + C[1][0]*C[1][0] + C[2][0]*C[2][0];
    float a11 = C[0][1]*C[0][1] + C[1][1]*C[1][1] + C[2][1]*C[2][1];
    float a22 = C[0][2]*C[0][2] + C[1][2]*C[1][2] + C[2][2]*C[2][2];
    float a01 = C[0][0]*C[0][1] + C[1][0]*C[1][1] + C[2][0]*C[2][1];
    float a02 = C[0][0]*C[0][2] + C[1][0]*C[1][2] + C[2][0]*C[2][2];
    float a12 = C[0][1]*C[0][2] + C[1][1]*C[1][2] + C[2][1]*C[2][2];

    float q  = (a00 + a11 + a22) * (1.f / 3.f);
    float p1 = a01*a01 + a02*a02 + a12*a12;
    float b00 = a00 - q, b11 = a11 - q, b22 = a22 - q;
    float p2 = b00*b00 + b11*b11 + b22*b22 + 2.f * p1;
    float p  = sqrtf(fmaxf(p2, 1e-30f) * (1.f / 6.f));
    float ip = 1.f / p;
    float detB = ( b00 * (b11*b22 - a12*a12)
                 - a01 * (a01*b22 - a12*a02)
                 + a02 * (a01*a12 - b11*a02) ) * (ip * ip * ip);
    float r = fminf(fmaxf(0.5f * detB, -1.f), 1.f);
    float phi = acosf(r) * (1.f / 3.f);
    float e0 = q + 2.f * p * cosf(phi);
    float e2 = q + 2.f * p * cosf(phi + 2.0943951023931953f);
    float e1 = 3.f * q - e0 - e2;

    float s0 = sqrtf(fmaxf(e0, 0.f));
    float s1 = sqrtf(fmaxf(e1, 0.f));
    float s2 = sqrtf(fmaxf(e2, 0.f));

    float detC = C[0][0]*(C[1][1]*C[2][2] - C[1][2]*C[2][1])
               - C[0][1]*(C[1][0]*C[2][2] - C[1][2]*C[2][0])
               + C[0][2]*(C[1][0]*C[2][1] - C[1][1]*C[2][0]);
    float sgn = (detC < 0.f) ? -1.f : 1.f;

    return sxy - 2.f * (s0 + s1 + sgn * s2);
}

__global__ __launch_bounds__(256)
void rmsd_fused_kernel(const char* __restrict__ xg, const char* __restrict__ yg,
                       float* __restrict__ out)
{
    extern __shared__ char smem[];                   // [WPB][DEPTH][x 6144 | y 6144]
    __shared__ unsigned long long mbar_store[WPB][DEPTH];
    __shared__ double wl[WPB];
    __shared__ int    is_last;

    const int tid  = threadIdx.x;
    const int w    = tid >> 5;
    const int lane = tid & 31;
    const int gw   = blockIdx.x * WPB + w;            // global warp pipeline id

    const unsigned smem_base = smem_u32(smem);
    const unsigned warp_smem = smem_base + w * DEPTH * SLOT_BYTES;
    const unsigned mb[2] = { smem_u32(&mbar_store[w][0]), smem_u32(&mbar_store[w][1]) };

    if (lane == 0) { mbar_init(mb[0], 1); mbar_init(mb[1], 1); }
    __syncthreads();   // all mbarriers initialized before any TMA

    const int total = (NB - gw + NW - 1) / NW;        // batches for this warp (6 or 7)

    auto issue = [&](int j) {                          // lane 0 only
        const int gb = gw + j * NW;
        const int slot = j & 1;
        const size_t goff = (size_t)gb * TBYTES;
        const unsigned dst = warp_smem + slot * SLOT_BYTES;
        mbar_expect_tx(mb[slot], SLOT_BYTES);
        bulk_cp(dst,          xg + goff, TBYTES, mb[slot]);
        bulk_cp(dst + TBYTES, yg + goff, TBYTES, mb[slot]);
    };

    if (lane == 0) {
        if (total > 0) issue(0);
        if (total > 1) issue(1);
    }
    __syncwarp();

    double local_loss = 0.0;

    for (int j = 0; j < total; j++) {
        const int slot = j & 1;
        mbar_wait(mb[slot], (j >> 1) & 1);            // all lanes acquire

        const float4* sx = reinterpret_cast<const float4*>(
            smem + (size_t)w * DEPTH * SLOT_BYTES + (size_t)slot * SLOT_BYTES);
        const float4* sy = sx + TBYTES / 16;

        float v[16];
#pragma unroll
        for (int i = 0; i < 16; i++) v[i] = 0.f;

#pragma unroll
        for (int c = 0; c < 4; c++) {
            const int g = c * 32 + lane;              // 4-point group
            float4 xa = sx[3*g], xb = sx[3*g + 1], xc = sx[3*g + 2];
            float4 ya = sy[3*g], yb = sy[3*g + 1], yc = sy[3*g + 2];

            float X[4][3] = {{xa.x, xa.y, xa.z}, {xa.w, xb.x, xb.y},
                             {xb.z, xb.w, xc.x}, {xc.y, xc.z, xc.w}};
            float Y[4][3] = {{ya.x, ya.y, ya.z}, {ya.w, yb.x, yb.y},
                             {yb.z, yb.w, yc.x}, {yc.y, yc.z, yc.w}};
#pragma unroll
            for (int pnt = 0; pnt < 4; pnt++) {
#pragma unroll
                for (int d = 0; d < 3; d++) {
                    v[d]     += X[pnt][d];
                    v[3 + d] += Y[pnt][d];
                    v[6]     += X[pnt][d] * X[pnt][d];
                    v[6]     += Y[pnt][d] * Y[pnt][d];
#pragma unroll
                    for (int e = 0; e < 3; e++)
                        v[7 + 3*d + e] += X[pnt][d] * Y[pnt][e];
                }
            }
        }

        // Slot contents fully in registers -> refill NOW, ahead of the
        // SHFL reduction tree, so the copy overlaps reduce + kabsch.
        __syncwarp();
        if (lane == 0 && j + DEPTH < total) issue(j + DEPTH);

        // Paired-value warp reduction: 8 pairs, 6 SHFL each + 1 gather.
        float fin[16];
#pragma unroll
        for (int i = 0; i < 8; i++) {
            float a = v[2*i]     + __shfl_xor_sync(0xffffffffu, v[2*i],     16);
            float b = v[2*i + 1] + __shfl_xor_sync(0xffffffffu, v[2*i + 1], 16);
            float c = (lane < 16) ? a : b;
#pragma unroll
            for (int o = 8; o > 0; o >>= 1)
                c += __shfl_xor_sync(0xffffffffu, c, o);
            float odd = __shfl_sync(0xffffffffu, c, 16);
            fin[2*i]     = c;      // valid on lane 0
            fin[2*i + 1] = odd;
        }

        if (lane == 0) local_loss += (double)kabsch_loss(fin);
    }

    if (lane == 0) wl[w] = local_loss;
    __syncthreads();

    if (tid == 0) {
        double s = 0.0;
#pragma unroll
        for (int i = 0; i < WPB; i++) s += wl[i];
        g_partial[blockIdx.x] = s;
        __threadfence();
        unsigned done = atomicAdd(&g_count, 1u);
        is_last = (done == GRID - 1) ? 1 : 0;
    }
    __syncthreads();

    if (is_last) {
        __threadfence();
        volatile double* gp = g_partial;
        double s = (tid < GRID) ? gp[tid] : 0.0;

#pragma unroll
        for (int o = 16; o > 0; o >>= 1)
            s += __shfl_down_sync(0xffffffffu, s, o);

        __shared__ double sm[8];
        if (lane == 0) sm[w] = s;
        __syncthreads();
        if (tid == 0) {
            double tot = 0.0;
#pragma unroll
            for (int i = 0; i < 8; i++) tot += sm[i];
            out[0] = (float)(tot / ((double)NB * 512.0 * 3.0));
            g_count = 0;   // reset for graph replay
        }
    }
}

extern "C" void kernel_launch(void* const* d_in, const int* in_sizes, int n_in,
                              void* d_out, int out_size)
{
    const char* inp = (const char*)d_in[0];
    const char* tgt = (const char*)d_in[1];
    float* out = (float*)d_out;

    static int configured = 0;
    if (!configured) {
        cudaFuncSetAttribute(rmsd_fused_kernel,
                             cudaFuncAttributeMaxDynamicSharedMemorySize, SMEM_BYTES);
        configured = 1;
    }
    rmsd_fused_kernel<<<GRID, 256, SMEM_BYTES>>>(inp, tgt, out);
}

// round 16
// speedup vs baseline: 1.1235x; 1.0152x over previous
#include <cuda_runtime.h>
#include <math.h>

// RMSD (Kabsch-aligned MSE). Per-WARP independent TMA pipelines (DEPTH=2),
// 8 warps/CTA, 148 persistent CTAs x 256 threads. Identical to the 18.9us
// best except: slot refill is issued immediately after the accumulate loop
// (before the SHFL reduction tree), shortening the copy-issue latency path.

constexpr int NB   = 8192;
constexpr int GRID = 148;
constexpr int WPB  = 8;                    // warps per CTA
constexpr int NW   = GRID * WPB;           // 1184 warp pipelines
constexpr int DEPTH = 2;                   // slots per warp
constexpr int TBYTES = 512 * 3 * 4;        // 6144 per tensor per batch
constexpr int SLOT_BYTES = 2 * TBYTES;     // 12288 (x | y)
constexpr int SMEM_BYTES = WPB * DEPTH * SLOT_BYTES;  // 196608

__device__ double       g_partial[GRID];
__device__ unsigned int g_count = 0;

__device__ __forceinline__ unsigned smem_u32(const void* p) {
    return (unsigned)__cvta_generic_to_shared(p);
}
__device__ __forceinline__ void bulk_cp(unsigned dst, const void* src, unsigned bytes,
                                        unsigned mbar) {
    asm volatile(
        "cp.async.bulk.shared::cluster.global.mbarrier::complete_tx::bytes "
        "[%0], [%1], %2, [%3];"
        :: "r"(dst), "l"(src), "r"(bytes), "r"(mbar) : "memory");
}
__device__ __forceinline__ void mbar_init(unsigned mbar, unsigned count) {
    asm volatile("mbarrier.init.shared.b64 [%0], %1;" :: "r"(mbar), "r"(count) : "memory");
}
__device__ __forceinline__ void mbar_expect_tx(unsigned mbar, unsigned tx) {
    asm volatile("mbarrier.arrive.expect_tx.shared.b64 _, [%0], %1;"
                 :: "r"(mbar), "r"(tx) : "memory");
}
__device__ __forceinline__ void mbar_wait(unsigned mbar, unsigned parity) {
    asm volatile(
        "{\n\t"
        ".reg .pred P;\n\t"
        "WAIT_%=:\n\t"
        "mbarrier.try_wait.parity.acquire.cta.shared::cta.b64 P, [%0], %1, 0x989680;\n\t"
        "@P bra.uni DONE_%=;\n\t"
        "bra.uni WAIT_%=;\n\t"
        "DONE_%=:\n\t"
        "}"
        :: "r"(mbar), "r"(parity) : "memory");
}

// fin[16]: 0-2 Sx, 3-5 Sy, 6 S|x|^2+S|y|^2, 7..15 raw C row-major
__device__ __forceinline__ float kabsch_loss(const float* fin)
{
    const float n = 512.f;
    const float invn = 1.f / n;
    float mx[3], my[3];
#pragma unroll
    for (int d = 0; d < 3; d++) { mx[d] = fin[d] * invn; my[d] = fin[3 + d] * invn; }

    float C[3][3];
#pragma unroll
    for (int d = 0; d < 3; d++)
#pragma unroll
        for (int e = 0; e < 3; e++)
            C[d][e] = fin[7 + 3*d + e] - n * mx[d] * my[e];

    float sxy = fin[6] - n * (mx[0]*mx[0] + mx[1]*mx[1] + mx[2]*mx[2]
                            + my[0]*my[0] + my[1]*my[1] + my[2]*my[2]);

    float a00 = C[0][0]*C[0][0] + C[1][0]*C[1][0] + C[2][0]*C[2][0];
    float a11 = C[0][1]*C[0][1] + C[1][1]*C[1][1] + C[2][1]*C[2][1];
    float a22 = C[0][2]*C[0][2] + C[1][2]*C[1][2] + C[2][2]*C[2][2];
    float a01 = C[0][0]*C[0][1] + C[1][0]*C[1][1] + C[2][0]*C[2][1];
    float a02 = C[0][0]*C[0][2] + C[1][0]*C[1][2] + C[2][0]*C[2][2];
    float a12 = C[0][1]*C[0][2] + C[1][1]*C[1][2] + C[2][1]*C[2][2];

    float q  = (a00 + a11 + a22) * (1.f / 3.f);
    float p1 = a01*a01 + a02*a02 + a12*a12;
    float b00 = a00 - q, b11 = a11 - q, b22 = a22 - q;
    float p2 = b00*b00 + b11*b11 + b22*b22 + 2.f * p1;
    float p  = sqrtf(fmaxf(p2, 1e-30f) * (1.f / 6.f));
    float ip = 1.f / p;
    float detB = ( b00 * (b11*b22 - a12*a12)
                 - a01 * (a01*b22 - a12*a02)
                 + a02 * (a01*a12 - b11*a02) ) * (ip * ip * ip);
    float r = fminf(fmaxf(0.5f * detB, -1.f), 1.f);
    float phi = acosf(r) * (1.f / 3.f);
    float e0 = q + 2.f * p * cosf(phi);
    float e2 = q + 2.f * p * cosf(phi + 2.0943951023931953f);
    float e1 = 3.f * q - e0 - e2;

    float s0 = sqrtf(fmaxf(e0, 0.f));
    float s1 = sqrtf(fmaxf(e1, 0.f));
    float s2 = sqrtf(fmaxf(e2, 0.f));

    float detC = C[0][0]*(C[1][1]*C[2][2] - C[1][2]*C[2][1])
               - C[0][1]*(C[1][0]*C[2][2] - C[1][2]*C[2][0])
               + C[0][2]*(C[1][0]*C[2][1] - C[1][1]*C[2][0]);
    float sgn = (detC < 0.f) ? -1.f : 1.f;

    return sxy - 2.f * (s0 + s1 + sgn * s2);
}

__global__ __launch_bounds__(256)
void rmsd_fused_kernel(const char* __restrict__ xg, const char* __restrict__ yg,
                       float* __restrict__ out)
{
    extern __shared__ char smem[];                   // [WPB][DEPTH][x 6144 | y 6144]
    __shared__ unsigned long long mbar_store[WPB][DEPTH];
    __shared__ double wl[WPB];
    __shared__ int    is_last;

    const int tid  = threadIdx.x;
    const int w    = tid >> 5;
    const int lane = tid & 31;
    const int gw   = blockIdx.x * WPB + w;            // global warp pipeline id

    const unsigned smem_base = smem_u32(smem);
    const unsigned warp_smem = smem_base + w * DEPTH * SLOT_BYTES;
    const unsigned mb[2] = { smem_u32(&mbar_store[w][0]), smem_u32(&mbar_store[w][1]) };

    if (lane == 0) { mbar_init(mb[0], 1); mbar_init(mb[1], 1); }
    __syncthreads();   // all mbarriers initialized before any TMA

    const int total = (NB - gw + NW - 1) / NW;        // batches for this warp (6 or 7)

    auto issue = [&](int j) {                          // lane 0 only
        const int gb = gw + j * NW;
        const int slot = j & 1;
        const size_t goff = (size_t)gb * TBYTES;
        const unsigned dst = warp_smem + slot * SLOT_BYTES;
        mbar_expect_tx(mb[slot], SLOT_BYTES);
        bulk_cp(dst,          xg + goff, TBYTES, mb[slot]);
        bulk_cp(dst + TBYTES, yg + goff, TBYTES, mb[slot]);
    };

    if (lane == 0) {
        if (total > 0) issue(0);
        if (total > 1) issue(1);
    }
    __syncwarp();

    double local_loss = 0.0;

    for (int j = 0; j < total; j++) {
        const int slot = j & 1;
        mbar_wait(mb[slot], (j >> 1) & 1);            // all lanes acquire

        const float4* sx = reinterpret_cast<const float4*>(
            smem + (size_t)w * DEPTH * SLOT_BYTES + (size_t)slot * SLOT_BYTES);
        const float4* sy = sx + TBYTES / 16;

        float v[16];
#pragma unroll
        for (int i = 0; i < 16; i++) v[i] = 0.f;

#pragma unroll
        for (int c = 0; c < 4; c++) {
            const int g = c * 32 + lane;              // 4-point group
            float4 xa = sx[3*g], xb = sx[3*g + 1], xc = sx[3*g + 2];
            float4 ya = sy[3*g], yb = sy[3*g + 1], yc = sy[3*g + 2];

            float X[4][3] = {{xa.x, xa.y, xa.z}, {xa.w, xb.x, xb.y},
                             {xb.z, xb.w, xc.x}, {xc.y, xc.z, xc.w}};
            float Y[4][3] = {{ya.x, ya.y, ya.z}, {ya.w, yb.x, yb.y},
                             {yb.z, yb.w, yc.x}, {yc.y, yc.z, yc.w}};
#pragma unroll
            for (int pnt = 0; pnt < 4; pnt++) {
#pragma unroll
                for (int d = 0; d < 3; d++) {
                    v[d]     += X[pnt][d];
                    v[3 + d] += Y[pnt][d];
                    v[6]     += X[pnt][d] * X[pnt][d];
                    v[6]     += Y[pnt][d] * Y[pnt][d];
#pragma unroll
                    for (int e = 0; e < 3; e++)
                        v[7 + 3*d + e] += X[pnt][d] * Y[pnt][e];
                }
            }
        }

        // Slot contents fully in registers -> refill NOW, ahead of the
        // SHFL reduction tree, so the copy overlaps reduce + kabsch.
        __syncwarp();
        if (lane == 0 && j + DEPTH < total) issue(j + DEPTH);

        // Paired-value warp reduction: 8 pairs, 6 SHFL each + 1 gather.
        float fin[16];
#pragma unroll
        for (int i = 0; i < 8; i++) {
            float a = v[2*i]     + __shfl_xor_sync(0xffffffffu, v[2*i],     16);
            float b = v[2*i + 1] + __shfl_xor_sync(0xffffffffu, v[2*i + 1], 16);
            float c = (lane < 16) ? a : b;
#pragma unroll
            for (int o = 8; o > 0; o >>= 1)
                c += __shfl_xor_sync(0xffffffffu, c, o);
            float odd = __shfl_sync(0xffffffffu, c, 16);
            fin[2*i]     = c;      // valid on lane 0
            fin[2*i + 1] = odd;
        }

        if (lane == 0) local_loss += (double)kabsch_loss(fin);
    }

    if (lane == 0) wl[w] = local_loss;
    __syncthreads();

    if (tid == 0) {
        double s = 0.0;
#pragma unroll
        for (int i = 0; i < WPB; i++) s += wl[i];
        g_partial[blockIdx.x] = s;
        __threadfence();
        unsigned done = atomicAdd(&g_count, 1u);
        is_last = (done == GRID - 1) ? 1 : 0;
    }
    __syncthreads();

    if (is_last) {
        __threadfence();
        volatile double* gp = g_partial;
        double s = (tid < GRID) ? gp[tid] : 0.0;

#pragma unroll
        for (int o = 16; o > 0; o >>= 1)
            s += __shfl_down_sync(0xffffffffu, s, o);

        __shared__ double sm[8];
        if (lane == 0) sm[w] = s;
        __syncthreads();
        if (tid == 0) {
            double tot = 0.0;
#pragma unroll
            for (int i = 0; i < 8; i++) tot += sm[i];
            out[0] = (float)(tot / ((double)NB * 512.0 * 3.0));
            g_count = 0;   // reset for graph replay
        }
    }
}

extern "C" void kernel_launch(void* const* d_in, const int* in_sizes, int n_in,
                              void* d_out, int out_size)
{
    const char* inp = (const char*)d_in[0];
    const char* tgt = (const char*)d_in[1];
    float* out = (float*)d_out;

    static int configured = 0;
    if (!configured) {
        cudaFuncSetAttribute(rmsd_fused_kernel,
                             cudaFuncAttributeMaxDynamicSharedMemorySize, SMEM_BYTES);
        configured = 1;
    }
    rmsd_fused_kernel<<<GRID, 256, SMEM_BYTES>>>(inp, tgt, out);
}